// round 9
// baseline (speedup 1.0000x reference)
#include <cuda_runtime.h>
#include <math.h>
#include <stdint.h>

// Problem constants
#define Bsz   4
#define T_LEN 2048
#define E_DIM 1024
#define H_NUM 16
#define D_DIM 64
#define M_TOT (Bsz * T_LEN)   // 8192

// Scratch (allocation-free: device globals)
__device__ float g_q[M_TOT * E_DIM];
__device__ float g_k[M_TOT * E_DIM];
__device__ float g_v[M_TOT * E_DIM];
__device__ float g_att[M_TOT * E_DIM];

// ---------------------------------------------------------------------------
// mma helpers (m16n8k8 tf32, 3-term hi/lo split for fp32 accuracy).
// Operands are pre-split and stored hi/lo-interleaved in smem (float2),
// so a fragment element is one LDS.64, no ALU at read time.
// ---------------------------------------------------------------------------
__device__ __forceinline__ float tf32_round(float x) {
    uint32_t u;
    asm("cvt.rna.tf32.f32 %0, %1;" : "=r"(u) : "f"(x));
    return __uint_as_float(u);
}

__device__ __forceinline__ float2 split2_tf32(float x) {
    float h = tf32_round(x);
    float l = tf32_round(x - h);
    return make_float2(h, l);
}

__device__ __forceinline__ void mma_tf32(float* d, const uint32_t* a, const uint32_t* b) {
    asm volatile(
        "mma.sync.aligned.m16n8k8.row.col.f32.tf32.tf32.f32 "
        "{%0,%1,%2,%3},{%4,%5,%6,%7},{%8,%9},{%0,%1,%2,%3};"
        : "+f"(d[0]), "+f"(d[1]), "+f"(d[2]), "+f"(d[3])
        : "r"(a[0]), "r"(a[1]), "r"(a[2]), "r"(a[3]), "r"(b[0]), "r"(b[1]));
}

// acc += A*B with 3-term split (lo*hi + hi*lo + hi*hi)
__device__ __forceinline__ void mma_split3(float* acc, const uint32_t* ahi, const uint32_t* alo,
                                           const uint32_t* bhi, const uint32_t* blo) {
    mma_tf32(acc, alo, bhi);
    mma_tf32(acc, ahi, blo);
    mma_tf32(acc, ahi, bhi);
}

// ---------------------------------------------------------------------------
// Tensor-core GEMM (3xTF32 split): C[M,N] = A[M,K] @ W[N,K]^T + bias[N]
// CTA tile 128x64x16, 256 threads = 8 warps (4 m x 2 n), warp tile 32x32.
// DYNAMIC smem (61.4 KB > 48 KB static limit), hi/lo interleaved,
// row stride 40 floats -> fragment LDS.64 conflict-free per 16-lane phase.
// ---------------------------------------------------------------------------
#define BM  128
#define BN  64
#define BK  16
#define GST 40   // smem row stride in floats (BK*2 interleaved + 8 pad)
#define GEMM_SMEM_FLOATS (2 * BM * GST + 2 * BN * GST)   // 15360 floats = 61440 B

__device__ __forceinline__
void gemm_bias_body(const float* __restrict__ A, const float* __restrict__ W,
                    const float* __restrict__ bias, float* __restrict__ C,
                    int m0, int n0)
{
    extern __shared__ float gsm[];
    float* Asm = gsm;                       // [2][BM][GST]
    float* Wsm = gsm + 2 * BM * GST;        // [2][BN][GST]

    const int tid  = threadIdx.x;
    const int lane = tid & 31;
    const int wid  = tid >> 5;
    const int g    = lane >> 2;        // groupID (0..7)
    const int c    = lane & 3;         // threadID_in_group (0..3)
    const int warp_m = wid & 3;        // 0..3
    const int warp_n = wid >> 2;       // 0..1
    const int m_off = warp_m * 32;
    const int n_off = warp_n * 32;

    const int lr = tid >> 2;           // 0..63 (A rows lr, lr+64)
    const int lc = tid & 3;            // float4 index in the 16-wide K slab

    const float* Abase  = A + (size_t)(m0 + lr) * E_DIM + lc * 4;
    const float* A2base = Abase + (size_t)64 * E_DIM;
    const float* Wbase  = W + (size_t)(n0 + lr) * E_DIM + lc * 4;

    float acc[2][4][4];
#pragma unroll
    for (int mt = 0; mt < 2; mt++)
#pragma unroll
        for (int nt = 0; nt < 4; nt++)
#pragma unroll
            for (int q = 0; q < 4; q++) acc[mt][nt][q] = 0.f;

    // Stage helper: split float4 into two interleaved float4s {h,l,h,l}
    auto stage4 = [&](float* dst, const float4& v) {
        float2 s0 = split2_tf32(v.x), s1 = split2_tf32(v.y);
        float2 s2 = split2_tf32(v.z), s3 = split2_tf32(v.w);
        *(float4*)(dst)     = make_float4(s0.x, s0.y, s1.x, s1.y);
        *(float4*)(dst + 4) = make_float4(s2.x, s2.y, s3.x, s3.y);
    };

    // Preload first K slab into buffer 0
    {
        float4 va0 = *(const float4*)(Abase);
        float4 va1 = *(const float4*)(A2base);
        float4 vw  = *(const float4*)(Wbase);
        stage4(&Asm[lr * GST + lc * 8], va0);
        stage4(&Asm[(lr + 64) * GST + lc * 8], va1);
        stage4(&Wsm[lr * GST + lc * 8], vw);
    }
    __syncthreads();

    int buf = 0;
    for (int k0 = BK; k0 <= E_DIM; k0 += BK) {
        float4 pa0, pa1, pw;
        const bool more = (k0 < E_DIM);
        if (more) {
            pa0 = *(const float4*)(Abase + k0);
            pa1 = *(const float4*)(A2base + k0);
            pw  = *(const float4*)(Wbase + k0);
        }

        const float* Ab = Asm + buf * BM * GST;
        const float* Wb = Wsm + buf * BN * GST;

#pragma unroll
        for (int ks = 0; ks < 2; ks++) {
            const int kb = ks * 8;

            uint32_t bhi[4][2], blo[4][2];
#pragma unroll
            for (int nt = 0; nt < 4; nt++) {
                const int nrow = n_off + nt * 8 + g;
                float2 b0 = *(const float2*)&Wb[nrow * GST + (kb + c) * 2];
                float2 b1 = *(const float2*)&Wb[nrow * GST + (kb + c + 4) * 2];
                bhi[nt][0] = __float_as_uint(b0.x); blo[nt][0] = __float_as_uint(b0.y);
                bhi[nt][1] = __float_as_uint(b1.x); blo[nt][1] = __float_as_uint(b1.y);
            }

#pragma unroll
            for (int mt = 0; mt < 2; mt++) {
                const int mb = m_off + mt * 16;
                uint32_t ahi[4], alo[4];
                float2 a0 = *(const float2*)&Ab[(mb + g) * GST + (kb + c) * 2];
                float2 a1 = *(const float2*)&Ab[(mb + g + 8) * GST + (kb + c) * 2];
                float2 a2 = *(const float2*)&Ab[(mb + g) * GST + (kb + c + 4) * 2];
                float2 a3 = *(const float2*)&Ab[(mb + g + 8) * GST + (kb + c + 4) * 2];
                ahi[0] = __float_as_uint(a0.x); alo[0] = __float_as_uint(a0.y);
                ahi[1] = __float_as_uint(a1.x); alo[1] = __float_as_uint(a1.y);
                ahi[2] = __float_as_uint(a2.x); alo[2] = __float_as_uint(a2.y);
                ahi[3] = __float_as_uint(a3.x); alo[3] = __float_as_uint(a3.y);

#pragma unroll
                for (int nt = 0; nt < 4; nt++)
                    mma_split3(acc[mt][nt], ahi, alo, bhi[nt], blo[nt]);
            }
        }

        if (more) {
            const int nbuf = buf ^ 1;
            float* An = Asm + nbuf * BM * GST;
            float* Wn = Wsm + nbuf * BN * GST;
            stage4(&An[lr * GST + lc * 8], pa0);
            stage4(&An[(lr + 64) * GST + lc * 8], pa1);
            stage4(&Wn[lr * GST + lc * 8], pw);
            __syncthreads();
            buf = nbuf;
        }
    }

    // Epilogue: bias + store
#pragma unroll
    for (int nt = 0; nt < 4; nt++) {
        const int col = n0 + n_off + nt * 8 + 2 * c;
        const float2 bb = *(const float2*)(bias + col);
#pragma unroll
        for (int mt = 0; mt < 2; mt++) {
            const int r0 = m0 + m_off + mt * 16 + g;
            float2 v0, v1;
            v0.x = acc[mt][nt][0] + bb.x; v0.y = acc[mt][nt][1] + bb.y;
            v1.x = acc[mt][nt][2] + bb.x; v1.y = acc[mt][nt][3] + bb.y;
            *(float2*)(C + (size_t)r0 * E_DIM + col)       = v0;
            *(float2*)(C + (size_t)(r0 + 8) * E_DIM + col) = v1;
        }
    }
}

__global__ __launch_bounds__(256, 2)
void qkv_gemm_kernel(const float* __restrict__ x,
                     const float* __restrict__ Wq, const float* __restrict__ bq,
                     const float* __restrict__ Wk, const float* __restrict__ bk,
                     const float* __restrict__ Wv, const float* __restrict__ bv,
                     float* __restrict__ q, float* __restrict__ k, float* __restrict__ v)
{
    const int which = blockIdx.z;
    const float* W = (which == 0) ? Wq : (which == 1) ? Wk : Wv;
    const float* b = (which == 0) ? bq : (which == 1) ? bk : bv;
    float*       C = (which == 0) ? q  : (which == 1) ? k  : v;
    gemm_bias_body(x, W, b, C, blockIdx.y * BM, blockIdx.x * BN);
}

__global__ __launch_bounds__(256, 2)
void out_gemm_kernel(const float* __restrict__ A, const float* __restrict__ W,
                     const float* __restrict__ bias, float* __restrict__ C)
{
    gemm_bias_body(A, W, bias, C, blockIdx.y * BM, blockIdx.x * BN);
}

// ---------------------------------------------------------------------------
// Tensor-core flash attention.
// CTA: 128 threads = 4 warps; 64-query tile; warp w owns rows w*16..w*16+15.
// K and V kept natural [key][d]; P per-warp. All smem operands stored
// hi/lo-interleaved (float2 per element), row stride 136 floats:
// fragment LDS.64 conflict-free. Splits happen once at stage/write time.
// Q pre-split into registers before the mainloop (loop-invariant).
// K/V tiles prefetched global->registers while previous tile computes.
// ---------------------------------------------------------------------------
#define ATTN_SCALE 0.125f   // 1/sqrt(64)
#define AST2 136            // smem row stride in floats (64*2 interleaved + 8 pad)

__global__ __launch_bounds__(128)
void attn_kernel()
{
    extern __shared__ float smem[];
    float* Ks = smem;                // [key][d]  interleaved hi/lo
    float* Vs = Ks + 64 * AST2;      // [key][d]  interleaved hi/lo
    float* Ps = Vs + 64 * AST2;      // [q][key]  interleaved hi/lo

    const int tid  = threadIdx.x;
    const int lane = tid & 31;
    const int w    = tid >> 5;      // warp 0..3
    const int g    = lane >> 2;     // 0..7
    const int c    = lane & 3;      // 0..3

    const int qt = blockIdx.x;      // query tile (0..31)
    const int h  = blockIdx.y;
    const int b  = blockIdx.z;

    const size_t rowbase = (size_t)b * T_LEN;
    const int hcol = h * D_DIM;

    const int qrow0 = qt * 64 + w * 16 + g;      // global q row (this thread, half 0)
    const int qrow1 = qrow0 + 8;

    // Load + pre-split Q fragments once (scaled, loop-invariant)
    uint32_t qh[8][4], ql[8][4];
#pragma unroll
    for (int kb = 0; kb < 8; kb++) {
        const int col0 = hcol + kb * 8 + c;
        float v0 = g_q[(rowbase + qrow0) * E_DIM + col0]     * ATTN_SCALE;
        float v1 = g_q[(rowbase + qrow1) * E_DIM + col0]     * ATTN_SCALE;
        float v2 = g_q[(rowbase + qrow0) * E_DIM + col0 + 4] * ATTN_SCALE;
        float v3 = g_q[(rowbase + qrow1) * E_DIM + col0 + 4] * ATTN_SCALE;
        float2 s0 = split2_tf32(v0), s1 = split2_tf32(v1);
        float2 s2 = split2_tf32(v2), s3 = split2_tf32(v3);
        qh[kb][0] = __float_as_uint(s0.x); ql[kb][0] = __float_as_uint(s0.y);
        qh[kb][1] = __float_as_uint(s1.x); ql[kb][1] = __float_as_uint(s1.y);
        qh[kb][2] = __float_as_uint(s2.x); ql[kb][2] = __float_as_uint(s2.y);
        qh[kb][3] = __float_as_uint(s3.x); ql[kb][3] = __float_as_uint(s3.y);
    }

    // Per-thread global-load slots: 8 rows x 1 float4, for K and V
    const int ld_row = tid >> 4;            // 0..7 base row
    const int ld_f4  = tid & 15;            // float4 column 0..15

    float o[8][4];                  // O accumulator: 8 d-tiles of m16n8
#pragma unroll
    for (int nt = 0; nt < 8; nt++)
#pragma unroll
        for (int q = 0; q < 4; q++) o[nt][q] = 0.f;
    float mrow[2] = {-1e30f, -1e30f};
    float lrow[2] = {0.f, 0.f};

    // Prefetch first K/V tile into registers
    float4 pk[8], pv[8];
#pragma unroll
    for (int it = 0; it < 8; it++) {
        const int row = ld_row + it * 8;
        const size_t grow = (rowbase + row) * E_DIM + hcol + ld_f4 * 4;
        pk[it] = *(const float4*)(g_k + grow);
        pv[it] = *(const float4*)(g_v + grow);
    }

    auto stage4 = [&](float* dst, const float4& v) {
        float2 s0 = split2_tf32(v.x), s1 = split2_tf32(v.y);
        float2 s2 = split2_tf32(v.z), s3 = split2_tf32(v.w);
        *(float4*)(dst)     = make_float4(s0.x, s0.y, s1.x, s1.y);
        *(float4*)(dst + 4) = make_float4(s2.x, s2.y, s3.x, s3.y);
    };

    for (int kt = 0; kt < T_LEN / 64; kt++) {
        __syncthreads();            // all warps done reading Ks/Vs from prev iter
        // Commit prefetched tile to smem, pre-split hi/lo interleaved
#pragma unroll
        for (int it = 0; it < 8; it++) {
            const int row = ld_row + it * 8;
            stage4(&Ks[row * AST2 + ld_f4 * 8], pk[it]);
            stage4(&Vs[row * AST2 + ld_f4 * 8], pv[it]);
        }
        __syncthreads();

        // Prefetch next tile (overlaps with compute below)
        if (kt + 1 < T_LEN / 64) {
#pragma unroll
            for (int it = 0; it < 8; it++) {
                const int row = (kt + 1) * 64 + ld_row + it * 8;
                const size_t grow = (rowbase + row) * E_DIM + hcol + ld_f4 * 4;
                pk[it] = *(const float4*)(g_k + grow);
                pv[it] = *(const float4*)(g_v + grow);
            }
        }

        // S = Q @ K^T : s[nt] covers keys nt*8..nt*8+7
        float s[8][4];
#pragma unroll
        for (int nt = 0; nt < 8; nt++)
#pragma unroll
            for (int q = 0; q < 4; q++) s[nt][q] = 0.f;

#pragma unroll
        for (int kb = 0; kb < 8; kb++) {
#pragma unroll
            for (int nt = 0; nt < 8; nt++) {
                float2 b0 = *(const float2*)&Ks[(nt * 8 + g) * AST2 + (kb * 8 + c) * 2];
                float2 b1 = *(const float2*)&Ks[(nt * 8 + g) * AST2 + (kb * 8 + c + 4) * 2];
                uint32_t bhi[2], blo[2];
                bhi[0] = __float_as_uint(b0.x); blo[0] = __float_as_uint(b0.y);
                bhi[1] = __float_as_uint(b1.x); blo[1] = __float_as_uint(b1.y);
                mma_split3(s[nt], qh[kb], ql[kb], bhi, blo);
            }
        }

        // Online softmax per row half (ri=0: row g; ri=1: row g+8)
#pragma unroll
        for (int ri = 0; ri < 2; ri++) {
            float mx = -1e30f;
#pragma unroll
            for (int nt = 0; nt < 8; nt++)
                mx = fmaxf(mx, fmaxf(s[nt][2 * ri], s[nt][2 * ri + 1]));
            mx = fmaxf(mx, __shfl_xor_sync(0xffffffffu, mx, 1));
            mx = fmaxf(mx, __shfl_xor_sync(0xffffffffu, mx, 2));
            const float mnew  = fmaxf(mrow[ri], mx);
            const float alpha = __expf(mrow[ri] - mnew);
            float rs = 0.f;
#pragma unroll
            for (int nt = 0; nt < 8; nt++) {
                s[nt][2 * ri]     = __expf(s[nt][2 * ri] - mnew);
                s[nt][2 * ri + 1] = __expf(s[nt][2 * ri + 1] - mnew);
                rs += s[nt][2 * ri] + s[nt][2 * ri + 1];
            }
            rs += __shfl_xor_sync(0xffffffffu, rs, 1);
            rs += __shfl_xor_sync(0xffffffffu, rs, 2);
            lrow[ri] = lrow[ri] * alpha + rs;
            mrow[ri] = mnew;
#pragma unroll
            for (int nt = 0; nt < 8; nt++) {
                o[nt][2 * ri]     *= alpha;
                o[nt][2 * ri + 1] *= alpha;
            }
        }

        // Write P to this warp's smem rows, pre-split hi/lo interleaved
        {
            const int pr0 = w * 16 + g;
#pragma unroll
            for (int nt = 0; nt < 8; nt++) {
                float2 p0 = split2_tf32(s[nt][0]);
                float2 p1 = split2_tf32(s[nt][1]);
                *(float4*)&Ps[pr0 * AST2 + (nt * 8 + 2 * c) * 2] =
                    make_float4(p0.x, p0.y, p1.x, p1.y);
                float2 p2 = split2_tf32(s[nt][2]);
                float2 p3 = split2_tf32(s[nt][3]);
                *(float4*)&Ps[(pr0 + 8) * AST2 + (nt * 8 + 2 * c) * 2] =
                    make_float4(p2.x, p2.y, p3.x, p3.y);
            }
        }
        __syncwarp();

        // O += P @ V : B operand read directly from natural Vs[key][d]
#pragma unroll
        for (int kb = 0; kb < 8; kb++) {
            const int pr0 = w * 16 + g;
            uint32_t phi[4], plo[4];
            {
                float2 a0 = *(const float2*)&Ps[pr0 * AST2 + (kb * 8 + c) * 2];
                float2 a1 = *(const float2*)&Ps[(pr0 + 8) * AST2 + (kb * 8 + c) * 2];
                float2 a2 = *(const float2*)&Ps[pr0 * AST2 + (kb * 8 + c + 4) * 2];
                float2 a3 = *(const float2*)&Ps[(pr0 + 8) * AST2 + (kb * 8 + c + 4) * 2];
                phi[0] = __float_as_uint(a0.x); plo[0] = __float_as_uint(a0.y);
                phi[1] = __float_as_uint(a1.x); plo[1] = __float_as_uint(a1.y);
                phi[2] = __float_as_uint(a2.x); plo[2] = __float_as_uint(a2.y);
                phi[3] = __float_as_uint(a3.x); plo[3] = __float_as_uint(a3.y);
            }
#pragma unroll
            for (int nt = 0; nt < 8; nt++) {
                float2 b0 = *(const float2*)&Vs[(kb * 8 + c) * AST2 + (nt * 8 + g) * 2];
                float2 b1 = *(const float2*)&Vs[(kb * 8 + c + 4) * AST2 + (nt * 8 + g) * 2];
                uint32_t bhi[2], blo[2];
                bhi[0] = __float_as_uint(b0.x); blo[0] = __float_as_uint(b0.y);
                bhi[1] = __float_as_uint(b1.x); blo[1] = __float_as_uint(b1.y);
                mma_split3(o[nt], phi, plo, bhi, blo);
            }
        }
        __syncwarp();   // Ps reads done before next iteration overwrites
    }

    // Normalize and write out
    const float inv0 = 1.f / lrow[0];
    const float inv1 = 1.f / lrow[1];
#pragma unroll
    for (int nt = 0; nt < 8; nt++) {
        const int col = hcol + nt * 8 + 2 * c;
        *(float2*)(g_att + (rowbase + qrow0) * E_DIM + col) =
            make_float2(o[nt][0] * inv0, o[nt][1] * inv0);
        *(float2*)(g_att + (rowbase + qrow1) * E_DIM + col) =
            make_float2(o[nt][2] * inv1, o[nt][3] * inv1);
    }
}

// ---------------------------------------------------------------------------
extern "C" void kernel_launch(void* const* d_in, const int* in_sizes, int n_in,
                              void* d_out, int out_size)
{
    const float* x  = (const float*)d_in[0];
    const float* Wq = (const float*)d_in[1];
    const float* bq = (const float*)d_in[2];
    const float* Wk = (const float*)d_in[3];
    const float* bk = (const float*)d_in[4];
    const float* Wv = (const float*)d_in[5];
    const float* bv = (const float*)d_in[6];
    const float* Wo = (const float*)d_in[7];
    const float* bo = (const float*)d_in[8];

    float *qp, *kp, *vp, *ap;
    cudaGetSymbolAddress((void**)&qp, g_q);
    cudaGetSymbolAddress((void**)&kp, g_k);
    cudaGetSymbolAddress((void**)&vp, g_v);
    cudaGetSymbolAddress((void**)&ap, g_att);

    const int gemm_smem = GEMM_SMEM_FLOATS * sizeof(float);   // 61440 B
    cudaFuncSetAttribute(qkv_gemm_kernel, cudaFuncAttributeMaxDynamicSharedMemorySize, gemm_smem);
    cudaFuncSetAttribute(out_gemm_kernel, cudaFuncAttributeMaxDynamicSharedMemorySize, gemm_smem);

    // Fused Q/K/V projections: one launch, z selects the projection.
    qkv_gemm_kernel<<<dim3(E_DIM / BN, M_TOT / BM, 3), 256, gemm_smem>>>(
        x, Wq, bq, Wk, bk, Wv, bv, qp, kp, vp);

    const int attn_smem = 3 * 64 * AST2 * sizeof(float);   // 104448 B
    cudaFuncSetAttribute(attn_kernel, cudaFuncAttributeMaxDynamicSharedMemorySize, attn_smem);
    attn_kernel<<<dim3(T_LEN / 64, H_NUM, Bsz), 128, attn_smem>>>();

    out_gemm_kernel<<<dim3(E_DIM / BN, M_TOT / BM), 256, gemm_smem>>>(ap, Wo, bo, (float*)d_out);
}